// round 6
// baseline (speedup 1.0000x reference)
#include <cuda_runtime.h>
#include <cstdint>

#define BATCH 8192
#define DIN   64
#define DMID  1024
#define DOUT  64
#define NK    4

// Scratch (allocation-free rule: __device__ globals)
__device__ uint32_t g_hiA[BATCH * DMID];
__device__ uint32_t g_loA[BATCH * DMID];
__device__ uint32_t g_hiB[BATCH * DMID];
__device__ uint32_t g_loB[BATCH * DMID];
__device__ uint32_t g_hiX[BATCH * DIN];
__device__ uint32_t g_loX[BATCH * DIN];
__device__ int      g_perm[BATCH];
__device__ int      g_segOffset[NK + 1];
__device__ int      g_tilePrefix[NK + 1];

// ---------------------------------------------------------------------------
// Prep: detect int32 vs int64 domains, counting-sort rows by domain.
// ---------------------------------------------------------------------------
__global__ void prep_kernel(const int* __restrict__ dom, int n) {
    __shared__ int cnt[NK];
    __shared__ int ofs[NK];
    __shared__ int is64flag;
    int tid = threadIdx.x;
    if (tid < NK) cnt[tid] = 0;
    if (tid == 0) is64flag = 1;
    __syncthreads();

    for (int i = tid; i < 64; i += blockDim.x)
        if (dom[2 * i + 1] != 0) atomicAnd(&is64flag, 0);
    __syncthreads();
    const int stride = is64flag ? 2 : 1;

    for (int i = tid; i < n; i += blockDim.x)
        atomicAdd(&cnt[dom[i * stride]], 1);
    __syncthreads();

    if (tid == 0) {
        int off = 0, toff = 0;
        for (int k = 0; k < NK; k++) {
            g_segOffset[k]  = off;
            g_tilePrefix[k] = toff;
            ofs[k] = off;
            off  += cnt[k];
            toff += (cnt[k] + 127) >> 7;
        }
        g_segOffset[NK]  = off;
        g_tilePrefix[NK] = toff;
    }
    __syncthreads();

    for (int i = tid; i < n; i += blockDim.x) {
        int d = dom[i * stride];
        int p = atomicAdd(&ofs[d], 1);
        g_perm[p] = i;
    }
}

// ---------------------------------------------------------------------------
// tf32 / cp.async helpers
// ---------------------------------------------------------------------------
__device__ __forceinline__ uint32_t f2tf32(float x) {
    uint32_t r;
    asm("cvt.rna.tf32.f32 %0, %1;" : "=r"(r) : "f"(x));
    return r;
}
__device__ __forceinline__ void split_tf32(float x, uint32_t& hi, uint32_t& lo) {
    hi = f2tf32(x);
    lo = f2tf32(x - __uint_as_float(hi));
}
__device__ __forceinline__ void mma_tf32(float* c, const uint32_t* a, const uint32_t* b) {
    asm volatile(
        "mma.sync.aligned.m16n8k8.row.col.f32.tf32.tf32.f32 "
        "{%0,%1,%2,%3}, {%4,%5,%6,%7}, {%8,%9}, {%0,%1,%2,%3};"
        : "+f"(c[0]), "+f"(c[1]), "+f"(c[2]), "+f"(c[3])
        : "r"(a[0]), "r"(a[1]), "r"(a[2]), "r"(a[3]), "r"(b[0]), "r"(b[1]));
}
__device__ __forceinline__ void cp_async16(uint32_t smem_addr, const void* gptr, int src_bytes) {
    asm volatile("cp.async.ca.shared.global [%0], [%1], 16, %2;"
                 :: "r"(smem_addr), "l"(gptr), "r"(src_bytes));
}
__device__ __forceinline__ void cp_commit() {
    asm volatile("cp.async.commit_group;");
}
template <int N>
__device__ __forceinline__ void cp_wait() {
    asm volatile("cp.async.wait_group %0;" :: "n"(N));
}

// ---------------------------------------------------------------------------
// Split a fp32 array into tf32 hi/lo (used once, for X).
// ---------------------------------------------------------------------------
__global__ void split_kernel(const float* __restrict__ src,
                             uint32_t* __restrict__ hi, uint32_t* __restrict__ lo,
                             int n) {
    for (int i = blockIdx.x * blockDim.x + threadIdx.x; i < n; i += gridDim.x * blockDim.x) {
        uint32_t h, l;
        split_tf32(src[i], h, l);
        hi[i] = h;
        lo[i] = l;
    }
}

// ---------------------------------------------------------------------------
// 3xTF32 tensor-core GEMM, cp.async double-buffered, pre-split activations.
//   A arrives as (AHi, ALo) tf32-in-uint32; W raw fp32 (B split in consumer).
//   Epilogue (WRITE_SPLIT) emits (CHi, CLo) for the next layer; the final
//   layer writes fp32 to C with scatter.
// CTA tile 128 x TN, K-tile 16, 2 smem stages, 8 warps.
//   TN=128: warp grid 2(m) x 4(n), MF=4 ; TN=64: 4(m) x 2(n), MF=2.
// A smem [m][k] stride 20; B smem [k][n] stride TN+8 (conflict-free LDS).
// ---------------------------------------------------------------------------
template <int TN, bool RELU, bool BRANCH, bool GATHER, bool SCATTER, bool WRITE_SPLIT>
__global__ __launch_bounds__(256) void gemm_tc_kernel(
    const uint32_t* __restrict__ AHi, const uint32_t* __restrict__ ALo,
    const float* __restrict__ Wb, const float* __restrict__ biasb,
    float* __restrict__ C, uint32_t* __restrict__ CHi, uint32_t* __restrict__ CLo,
    int M, int Kd, int N)
{
    constexpr int TM = 128, KT = 16;
    constexpr int AP = 20;        // A smem row stride (words)
    constexpr int BP = TN + 8;    // B smem row stride (floats)
    constexpr int WMC = (TN == 128) ? 2 : 4;
    constexpr int WMS = TM / WMC;
    constexpr int MF  = WMS / 16;
    constexpr int NF  = 4;
    constexpr int ACH = TM * KT / 4;           // 512 16B chunks per A buffer
    constexpr int BCH = KT * TN / 4;
    constexpr int AW  = TM * AP;               // words per A buffer
    constexpr int STAGE_W = 2 * AW + KT * BP;  // words per stage

    extern __shared__ uint32_t dynsmem[];
    __shared__ int sPerm[TM];

    const int tid  = threadIdx.x;
    const int lane = tid & 31;
    const int warp = tid >> 5;
    const int wm   = warp % WMC;
    const int wn   = warp / WMC;
    const int colBase = blockIdx.x * TN;

    int rowBase, rowEnd, dom = 0;
    if (BRANCH) {
        const int t = blockIdx.y;
        if (t >= g_tilePrefix[NK]) return;   // uniform across CTA
        int k = 0;
#pragma unroll
        for (int j = 1; j < NK; j++)
            if (t >= g_tilePrefix[j]) k = j;
        dom = k;
        rowBase = g_segOffset[k] + (t - g_tilePrefix[k]) * TM;
        rowEnd  = g_segOffset[k + 1];
    } else {
        rowBase = blockIdx.y * TM;
        rowEnd  = M;
    }

    const float* W    = Wb    + (size_t)dom * Kd * N;
    const float* bias = biasb + (size_t)dom * N;

    if (GATHER || SCATTER) {
        for (int i = tid; i < TM; i += 256) {
            int r = rowBase + i;
            sPerm[i] = (r < rowEnd) ? g_perm[r] : -1;
        }
        __syncthreads();
    }

    const uint32_t smBase = (uint32_t)__cvta_generic_to_shared(dynsmem);

    // ---- Tile loader: cp.async stage 'st' from k-offset k0 ----
    auto load_tile = [&](int k0, int st) {
        const uint32_t sH = smBase + (st * STAGE_W) * 4;
        const uint32_t sL = sH + AW * 4;
        const uint32_t sB = sL + AW * 4;
#pragma unroll
        for (int c = tid; c < ACH; c += 256) {
            const int m  = c >> 2;
            const int kc = (c & 3) * 4;
            const int r  = rowBase + m;
            const bool ok = (r < rowEnd);
            const int gr = ok ? (GATHER ? sPerm[m] : r) : 0;
            const size_t goff = (size_t)gr * Kd + k0 + kc;
            const uint32_t soff = (m * AP + kc) * 4;
            cp_async16(sH + soff, AHi + goff, ok ? 16 : 0);
            cp_async16(sL + soff, ALo + goff, ok ? 16 : 0);
        }
#pragma unroll
        for (int c = tid; c < BCH; c += 256) {
            const int kr = c / (TN / 4);
            const int nc = (c % (TN / 4)) * 4;
            cp_async16(sB + (kr * BP + nc) * 4,
                       W + (size_t)(k0 + kr) * N + colBase + nc, 16);
        }
        cp_commit();
    };

    float acc[MF][NF][4];
#pragma unroll
    for (int i = 0; i < MF; i++)
#pragma unroll
        for (int j = 0; j < NF; j++)
#pragma unroll
            for (int q = 0; q < 4; q++) acc[i][j][q] = 0.f;

    const int r0 = lane >> 2;
    const int kq = lane & 3;
    const int nTiles = Kd / KT;

    load_tile(0, 0);

    for (int t = 0; t < nTiles; t++) {
        if (t + 1 < nTiles) load_tile((t + 1) * KT, (t + 1) & 1);
        if (t + 1 < nTiles) cp_wait<1>(); else cp_wait<0>();
        __syncthreads();

        const uint32_t* asH = dynsmem + (t & 1) * STAGE_W;
        const uint32_t* asL = asH + AW;
        const float*    bs  = reinterpret_cast<const float*>(asL + AW);

#pragma unroll
        for (int ks = 0; ks < KT; ks += 8) {
            uint32_t ah[MF][4], al[MF][4], bh[NF][2], bl[NF][2];
#pragma unroll
            for (int mf = 0; mf < MF; mf++) {
                const int mb = wm * WMS + mf * 16;
                const int i0 = (mb + r0) * AP + ks + kq;
                const int i1 = (mb + r0 + 8) * AP + ks + kq;
                ah[mf][0] = asH[i0];     al[mf][0] = asL[i0];
                ah[mf][1] = asH[i1];     al[mf][1] = asL[i1];
                ah[mf][2] = asH[i0 + 4]; al[mf][2] = asL[i0 + 4];
                ah[mf][3] = asH[i1 + 4]; al[mf][3] = asL[i1 + 4];
            }
#pragma unroll
            for (int nf = 0; nf < NF; nf++) {
                const int nb = wn * 32 + nf * 8 + r0;
                split_tf32(bs[(ks + kq) * BP + nb],     bh[nf][0], bl[nf][0]);
                split_tf32(bs[(ks + kq + 4) * BP + nb], bh[nf][1], bl[nf][1]);
            }
#pragma unroll
            for (int mf = 0; mf < MF; mf++)
#pragma unroll
                for (int nf = 0; nf < NF; nf++) {
                    mma_tf32(acc[mf][nf], ah[mf], bh[nf]);
                    mma_tf32(acc[mf][nf], ah[mf], bl[nf]);
                    mma_tf32(acc[mf][nf], al[mf], bh[nf]);
                }
        }
        __syncthreads();
    }

    // ---- Epilogue: bias (+ReLU); split-write or fp32 store (+scatter) ----
#pragma unroll
    for (int nf = 0; nf < NF; nf++) {
        const int col = colBase + wn * 32 + nf * 8 + (lane & 3) * 2;
        const float b0 = bias[col];
        const float b1 = bias[col + 1];
#pragma unroll
        for (int mf = 0; mf < MF; mf++) {
#pragma unroll
            for (int half = 0; half < 2; half++) {
                const int li = wm * WMS + mf * 16 + (lane >> 2) + half * 8;
                const int r  = rowBase + li;
                if (r < rowEnd) {
                    const int orow = SCATTER ? sPerm[li] : r;
                    float y0 = acc[mf][nf][half * 2 + 0] + b0;
                    float y1 = acc[mf][nf][half * 2 + 1] + b1;
                    if (RELU) {
                        y0 = fmaxf(y0, 0.f);
                        y1 = fmaxf(y1, 0.f);
                    }
                    const size_t off = (size_t)orow * N + col;
                    if (WRITE_SPLIT) {
                        uint32_t h0, l0, h1, l1;
                        split_tf32(y0, h0, l0);
                        split_tf32(y1, h1, l1);
                        *reinterpret_cast<uint2*>(CHi + off) = make_uint2(h0, h1);
                        *reinterpret_cast<uint2*>(CLo + off) = make_uint2(l0, l1);
                    } else {
                        *reinterpret_cast<float2*>(C + off) = make_float2(y0, y1);
                    }
                }
            }
        }
    }
}

// ---------------------------------------------------------------------------
extern "C" void kernel_launch(void* const* d_in, const int* in_sizes, int n_in,
                              void* d_out, int out_size) {
    const float* X   = (const float*)d_in[0];
    const int*   dm  = (const int*)  d_in[1];
    const float* W1  = (const float*)d_in[2];
    const float* b1  = (const float*)d_in[3];
    const float* W2  = (const float*)d_in[4];
    const float* b2  = (const float*)d_in[5];
    const float* W3  = (const float*)d_in[6];
    const float* b3  = (const float*)d_in[7];
    const float* W4  = (const float*)d_in[8];
    const float* b4  = (const float*)d_in[9];
    const float* BW1 = (const float*)d_in[10];
    const float* Bb1 = (const float*)d_in[11];
    const float* BW2 = (const float*)d_in[12];
    const float* Bb2 = (const float*)d_in[13];
    const float* BW3 = (const float*)d_in[14];
    const float* Bb3 = (const float*)d_in[15];
    const float* BW4 = (const float*)d_in[16];
    const float* Bb4 = (const float*)d_in[17];
    float* out = (float*)d_out;

    uint32_t *hiA, *loA, *hiB, *loB, *hiX, *loX;
    cudaGetSymbolAddress((void**)&hiA, g_hiA);
    cudaGetSymbolAddress((void**)&loA, g_loA);
    cudaGetSymbolAddress((void**)&hiB, g_hiB);
    cudaGetSymbolAddress((void**)&loB, g_loB);
    cudaGetSymbolAddress((void**)&hiX, g_hiX);
    cudaGetSymbolAddress((void**)&loX, g_loX);

    // Dynamic smem sizes (words -> bytes): 2 stages of (2*128*20 + 16*(TN+8))
    const int SMEM128 = (2 * (2 * 128 * 20 + 16 * 136)) * 4;   // 58368 B
    const int SMEM64  = (2 * (2 * 128 * 20 + 16 * 72))  * 4;   // 50176 B

    auto kMain = gemm_tc_kernel<128, true,  false, false, false, true>;
    auto kBr1  = gemm_tc_kernel<128, true,  true,  true,  false, true>;
    auto kBrM  = gemm_tc_kernel<128, true,  true,  false, false, true>;
    auto kBr4  = gemm_tc_kernel<64,  false, true,  false, true,  false>;
    cudaFuncSetAttribute(kMain, cudaFuncAttributeMaxDynamicSharedMemorySize, SMEM128);
    cudaFuncSetAttribute(kBr1,  cudaFuncAttributeMaxDynamicSharedMemorySize, SMEM128);
    cudaFuncSetAttribute(kBrM,  cudaFuncAttributeMaxDynamicSharedMemorySize, SMEM128);
    cudaFuncSetAttribute(kBr4,  cudaFuncAttributeMaxDynamicSharedMemorySize, SMEM64);

    const dim3 blk(256);
    const dim3 gridMain(DMID / 128, BATCH / 128);          // (8, 64)
    const int  btiles = BATCH / 128 + NK;                  // 68 padded row tiles
    const dim3 gridBr(DMID / 128, btiles);                 // (8, 68)
    const dim3 gridBr4(DOUT / 64, btiles);                 // (1, 68)

    prep_kernel<<<1, 256>>>(dm, BATCH);
    split_kernel<<<256, 256>>>(X, hiX, loX, BATCH * DIN);

    // Shared stack: Xsplit -> A -> B -> A -> B   (H4 ends in hiB/loB)
    kMain<<<gridMain, blk, SMEM128>>>(hiX, loX, W1, b1, nullptr, hiA, loA, BATCH, DIN,  DMID);
    kMain<<<gridMain, blk, SMEM128>>>(hiA, loA, W2, b2, nullptr, hiB, loB, BATCH, DMID, DMID);
    kMain<<<gridMain, blk, SMEM128>>>(hiB, loB, W3, b3, nullptr, hiA, loA, BATCH, DMID, DMID);
    kMain<<<gridMain, blk, SMEM128>>>(hiA, loA, W4, b4, nullptr, hiB, loB, BATCH, DMID, DMID);

    // Routed branches (each row through exactly its domain's branch)
    kBr1<<<gridBr,  blk, SMEM128>>>(hiB, loB, BW1, Bb1, nullptr, hiA, loA, BATCH, DMID, DMID);
    kBrM<<<gridBr,  blk, SMEM128>>>(hiA, loA, BW2, Bb2, nullptr, hiB, loB, BATCH, DMID, DMID);
    kBrM<<<gridBr,  blk, SMEM128>>>(hiB, loB, BW3, Bb3, nullptr, hiA, loA, BATCH, DMID, DMID);
    kBr4<<<gridBr4, blk, SMEM64>>>(hiA, loA, BW4, Bb4, out, nullptr, nullptr, BATCH, DMID, DOUT);
}